// round 2
// baseline (speedup 1.0000x reference)
#include <cuda_runtime.h>
#include <math.h>

#define CB 4
#define CS 2048
#define CD 512
#define CH 8
#define CDK 64
#define CM (CB*CS)      // 8192
#define CBH (CB*CH)     // 32

// ---------------- scratch (device globals: allocation-free) ----------------
static __device__ float g_xq[CM*CD];
static __device__ float g_xk[CM*CD];
static __device__ float g_q[CM*CD];
static __device__ float g_k[CM*CD];
static __device__ float g_v[CM*CD];
static __device__ float g_gate[CM*CD];
static __device__ float g_ao[CM*CD];
static __device__ float g_attn[(size_t)CBH*CS*CS];   // 512 MB raw scores
static __device__ float g_rmax[CBH*CS];
static __device__ float g_rsum[CBH*CS];   // stored as reciprocal of row sum
static __device__ float g_cmax[CBH*CS];
static __device__ float g_csum[CBH*CS];   // stored as reciprocal of col sum

// ---------------- fast exp (FFMA pipe, avoids MUFU bottleneck) ----------------
__device__ __forceinline__ float fast_exp(float x) {
    x = fmaxf(x, -80.0f);
    float t  = x * 1.4426950408889634f;   // x * log2(e)
    float fi = floorf(t);
    float f  = t - fi;                    // f in [0,1)
    float p  = 1.53533e-4f;
    p = fmaf(p, f, 1.33989e-3f);
    p = fmaf(p, f, 9.61844e-3f);
    p = fmaf(p, f, 5.55033e-2f);
    p = fmaf(p, f, 2.40226e-1f);
    p = fmaf(p, f, 6.93147e-1f);
    p = fmaf(p, f, 1.0f);
    return __int_as_float(((int)fi + 127) << 23) * p;
}

// ---------------- LayerNorm: one block per row, writes g_xq / g_xk ----------------
__global__ __launch_bounds__(256)
void ln_kernel(const float* __restrict__ xq, const float* __restrict__ xk,
               const float* __restrict__ gamma, const float* __restrict__ beta)
{
    int row = blockIdx.x;
    const float* x; float* o;
    if (row < CM) { x = xq + (size_t)row*CD;       o = g_xq + (size_t)row*CD; }
    else          { x = xk + (size_t)(row-CM)*CD;  o = g_xk + (size_t)(row-CM)*CD; }
    int t = threadIdx.x;                  // 256 threads, D=512 -> float2 each
    float2 v2 = ((const float2*)x)[t];
    float s  = v2.x + v2.y;
    float ss = v2.x*v2.x + v2.y*v2.y;
    #pragma unroll
    for (int off = 16; off; off >>= 1) {
        s  += __shfl_xor_sync(0xffffffffu, s,  off);
        ss += __shfl_xor_sync(0xffffffffu, ss, off);
    }
    __shared__ float sh_s[8], sh_ss[8];
    __shared__ float s_mean, s_rstd;
    int wid = t >> 5, lid = t & 31;
    if (lid == 0) { sh_s[wid] = s; sh_ss[wid] = ss; }
    __syncthreads();
    if (t < 32) {
        float a = (t < 8) ? sh_s[t]  : 0.f;
        float b = (t < 8) ? sh_ss[t] : 0.f;
        #pragma unroll
        for (int off = 4; off; off >>= 1) {
            a += __shfl_xor_sync(0xffffffffu, a, off);
            b += __shfl_xor_sync(0xffffffffu, b, off);
        }
        if (t == 0) {
            float mean = a * (1.0f/CD);
            float var  = b * (1.0f/CD) - mean*mean;
            s_mean = mean;
            s_rstd = rsqrtf(var + 1e-6f);
        }
    }
    __syncthreads();
    float mean = s_mean, rstd = s_rstd;
    float2 g2 = ((const float2*)gamma)[t];
    float2 b2 = ((const float2*)beta)[t];
    float2 o2;
    o2.x = (v2.x - mean) * rstd * g2.x + b2.x;
    o2.y = (v2.y - mean) * rstd * g2.y + b2.y;
    ((float2*)o)[t] = o2;
}

// ---------------- generic NT GEMM: C[m,n] = sum_k A[m,k]*W[n,k] (+bias)(+sigmoid)
// which: 0: A=g_xq C=g_q | 1: A=g_xk C=g_k | 2: A=g_xk C=g_v | 3: A=g_xq C=g_gate
//        4: A=g_ao C=Cext
__global__ __launch_bounds__(256)
void gemm_nt_kernel(int which, const float* __restrict__ W,
                    const float* __restrict__ bias, int act,
                    float* __restrict__ Cext)
{
    const float* A; float* C;
    switch (which) {
        case 0: A = g_xq; C = g_q;    break;
        case 1: A = g_xk; C = g_k;    break;
        case 2: A = g_xk; C = g_v;    break;
        case 3: A = g_xq; C = g_gate; break;
        default: A = g_ao; C = Cext;  break;
    }
    __shared__ float As[16][64];
    __shared__ float Bs[16][64];
    int tid = threadIdx.x;
    int tx = tid & 15, ty = tid >> 4;
    int m0 = blockIdx.y * 64, n0 = blockIdx.x * 64;
    const float* Ab = A + (size_t)m0 * CD;
    const float* Bb = W + (size_t)n0 * CD;
    int lm = tid >> 2, lk = (tid & 3) * 4;
    float acc[4][4] = {};
    for (int k0 = 0; k0 < CD; k0 += 16) {
        float4 a = *(const float4*)(Ab + (size_t)lm*CD + k0 + lk);
        float4 b = *(const float4*)(Bb + (size_t)lm*CD + k0 + lk);
        As[lk+0][lm]=a.x; As[lk+1][lm]=a.y; As[lk+2][lm]=a.z; As[lk+3][lm]=a.w;
        Bs[lk+0][lm]=b.x; Bs[lk+1][lm]=b.y; Bs[lk+2][lm]=b.z; Bs[lk+3][lm]=b.w;
        __syncthreads();
        #pragma unroll
        for (int kk = 0; kk < 16; kk++) {
            float4 av = *(const float4*)&As[kk][ty*4];
            float4 bv = *(const float4*)&Bs[kk][tx*4];
            float am[4] = {av.x, av.y, av.z, av.w};
            float bn[4] = {bv.x, bv.y, bv.z, bv.w};
            #pragma unroll
            for (int i = 0; i < 4; i++)
                #pragma unroll
                for (int j = 0; j < 4; j++)
                    acc[i][j] = fmaf(am[i], bn[j], acc[i][j]);
        }
        __syncthreads();
    }
    #pragma unroll
    for (int i = 0; i < 4; i++) {
        int m = m0 + ty*4 + i;
        #pragma unroll
        for (int j = 0; j < 4; j++) {
            int n = n0 + tx*4 + j;
            float v = acc[i][j];
            if (bias) v += bias[n];
            if (act == 1) v = 1.0f / (1.0f + __expf(-v));
            C[(size_t)m*CD + n] = v;
        }
    }
}

// ---------------- scores: attn[z, s, t] = q[b,s,h,:]·k[b,t,h,:] / 8 ----------------
__global__ __launch_bounds__(256)
void scores_kernel()
{
    __shared__ float As[16][64];
    __shared__ float Bs[16][64];
    int z = blockIdx.z;
    int b = z >> 3, h = z & 7;
    const float* Qb = g_q + (size_t)b*CS*CD + h*CDK;
    const float* Kb = g_k + (size_t)b*CS*CD + h*CDK;
    float* Cb = g_attn + (size_t)z*CS*CS;
    int tid = threadIdx.x;
    int tx = tid & 15, ty = tid >> 4;
    int m0 = blockIdx.y * 64, n0 = blockIdx.x * 64;
    int lm = tid >> 2, lk = (tid & 3) * 4;
    float acc[4][4] = {};
    #pragma unroll
    for (int k0 = 0; k0 < CDK; k0 += 16) {
        float4 a  = *(const float4*)(Qb + (size_t)(m0+lm)*CD + k0 + lk);
        float4 bb = *(const float4*)(Kb + (size_t)(n0+lm)*CD + k0 + lk);
        As[lk+0][lm]=a.x;  As[lk+1][lm]=a.y;  As[lk+2][lm]=a.z;  As[lk+3][lm]=a.w;
        Bs[lk+0][lm]=bb.x; Bs[lk+1][lm]=bb.y; Bs[lk+2][lm]=bb.z; Bs[lk+3][lm]=bb.w;
        __syncthreads();
        #pragma unroll
        for (int kk = 0; kk < 16; kk++) {
            float4 av = *(const float4*)&As[kk][ty*4];
            float4 bv = *(const float4*)&Bs[kk][tx*4];
            float am[4] = {av.x, av.y, av.z, av.w};
            float bn[4] = {bv.x, bv.y, bv.z, bv.w};
            #pragma unroll
            for (int i = 0; i < 4; i++)
                #pragma unroll
                for (int j = 0; j < 4; j++)
                    acc[i][j] = fmaf(am[i], bn[j], acc[i][j]);
        }
        __syncthreads();
    }
    #pragma unroll
    for (int i = 0; i < 4; i++) {
        int m = m0 + ty*4 + i;
        #pragma unroll
        for (int j = 0; j < 4; j++) {
            int n = n0 + tx*4 + j;
            Cb[(size_t)m*CS + n] = acc[i][j] * 0.125f;
        }
    }
}

// ---------------- row stats: online (max, sum exp) per row; one warp / row ----
__global__ __launch_bounds__(256)
void row_stats_kernel()
{
    int row  = blockIdx.x * 8 + (threadIdx.x >> 5);
    int lane = threadIdx.x & 31;
    const float* p = g_attn + (size_t)row * CS;
    float m = -1e30f, s = 0.f;
    #pragma unroll 4
    for (int t = lane; t < CS; t += 32) {
        float x  = p[t];
        float mn = fmaxf(m, x);
        s = s * fast_exp(m - mn) + fast_exp(x - mn);
        m = mn;
    }
    #pragma unroll
    for (int off = 16; off; off >>= 1) {
        float m2 = __shfl_xor_sync(0xffffffffu, m, off);
        float s2 = __shfl_xor_sync(0xffffffffu, s, off);
        float mn = fmaxf(m, m2);
        s = s * fast_exp(m - mn) + s2 * fast_exp(m2 - mn);
        m = mn;
    }
    if (lane == 0) { g_rmax[row] = m; g_rsum[row] = 1.0f / s; }
}

// ---------------- col stats: one thread per column, 4-way ILP online ----------
__global__ __launch_bounds__(256)
void col_stats_kernel()
{
    int z = blockIdx.y;
    int t = blockIdx.x * 256 + threadIdx.x;
    const float* p = g_attn + (size_t)z*CS*CS + t;
    float m0=-1e30f, m1=-1e30f, m2=-1e30f, m3=-1e30f;
    float s0=0.f, s1=0.f, s2=0.f, s3=0.f;
    for (int r = 0; r < CS; r += 4) {
        float x0 = p[(size_t)(r+0)*CS];
        float x1 = p[(size_t)(r+1)*CS];
        float x2 = p[(size_t)(r+2)*CS];
        float x3 = p[(size_t)(r+3)*CS];
        float n0 = fmaxf(m0,x0); s0 = s0*fast_exp(m0-n0) + fast_exp(x0-n0); m0 = n0;
        float n1 = fmaxf(m1,x1); s1 = s1*fast_exp(m1-n1) + fast_exp(x1-n1); m1 = n1;
        float n2 = fmaxf(m2,x2); s2 = s2*fast_exp(m2-n2) + fast_exp(x2-n2); m2 = n2;
        float n3 = fmaxf(m3,x3); s3 = s3*fast_exp(m3-n3) + fast_exp(x3-n3); m3 = n3;
    }
    float m = fmaxf(fmaxf(m0,m1), fmaxf(m2,m3));
    float s = s0*fast_exp(m0-m) + s1*fast_exp(m1-m) + s2*fast_exp(m2-m) + s3*fast_exp(m3-m);
    g_cmax[z*CS + t] = m;
    g_csum[z*CS + t] = 1.0f / s;
}

// ---------------- PV: out = (P @ V) with P built on-the-fly, gate fused ------
__global__ __launch_bounds__(256)
void pv_kernel()
{
    __shared__ float Ps[64][65];   // [t][s], padded against conflicts
    __shared__ float Vs[64][64];   // [t][dk]
    int z = blockIdx.y;
    int b = z >> 3, h = z & 7;
    int s0 = blockIdx.x * 64;
    const float* Araw = g_attn + (size_t)z*CS*CS;
    const float* Vb   = g_v    + (size_t)b*CS*CD + h*CDK;
    const float* Gb   = g_gate + (size_t)b*CS*CD + h*CDK;
    float*       Ob   = g_ao   + (size_t)b*CS*CD + h*CDK;
    int tid = threadIdx.x;
    int tx = tid & 15, ty = tid >> 4;
    int lr = tid >> 4;          // 0..15
    int lc = (tid & 15) * 4;    // 0..60 step 4
    float acc[4][4] = {};

    for (int t0 = 0; t0 < CS; t0 += 64) {
        // P tile (rows s0..+64, cols t0..+64), transformed:
        // p = exp(2x - rmax[s] - cmax[t]) * csum_inv[t]
        #pragma unroll
        for (int i = 0; i < 4; i++) {
            int r = lr + i*16;
            float4 x = *(const float4*)(Araw + (size_t)(s0+r)*CS + t0 + lc);
            float rm = g_rmax[z*CS + s0 + r];
            float cm0 = g_cmax[z*CS + t0 + lc+0], ci0 = g_csum[z*CS + t0 + lc+0];
            float cm1 = g_cmax[z*CS + t0 + lc+1], ci1 = g_csum[z*CS + t0 + lc+1];
            float cm2 = g_cmax[z*CS + t0 + lc+2], ci2 = g_csum[z*CS + t0 + lc+2];
            float cm3 = g_cmax[z*CS + t0 + lc+3], ci3 = g_csum[z*CS + t0 + lc+3];
            Ps[lc+0][r] = fast_exp(2.0f*x.x - rm - cm0) * ci0;
            Ps[lc+1][r] = fast_exp(2.0f*x.y - rm - cm1) * ci1;
            Ps[lc+2][r] = fast_exp(2.0f*x.z - rm - cm2) * ci2;
            Ps[lc+3][r] = fast_exp(2.0f*x.w - rm - cm3) * ci3;
        }
        // V tile (rows t0..+64, cols 0..64)
        #pragma unroll
        for (int i = 0; i < 4; i++) {
            int r = lr + i*16;
            float4 v4 = *(const float4*)(Vb + (size_t)(t0+r)*CD + lc);
            *(float4*)&Vs[r][lc] = v4;
        }
        __syncthreads();
        #pragma unroll
        for (int kk = 0; kk < 64; kk++) {
            float am[4];
            #pragma unroll
            for (int i = 0; i < 4; i++) am[i] = Ps[kk][ty*4 + i];
            float4 bv = *(const float4*)&Vs[kk][tx*4];
            float bn[4] = {bv.x, bv.y, bv.z, bv.w};
            #pragma unroll
            for (int i = 0; i < 4; i++)
                #pragma unroll
                for (int j = 0; j < 4; j++)
                    acc[i][j] = fmaf(am[i], bn[j], acc[i][j]);
        }
        __syncthreads();
    }
    #pragma unroll
    for (int i = 0; i < 4; i++) {
        int srow = s0 + ty*4 + i;
        float ri = g_rsum[z*CS + srow];   // reciprocal of row sum
        #pragma unroll
        for (int j = 0; j < 4; j++) {
            int dk = tx*4 + j;
            float val = acc[i][j] * ri * Gb[(size_t)srow*CD + dk];
            Ob[(size_t)srow*CD + dk] = val;
        }
    }
}

// ---------------- launch ----------------
extern "C" void kernel_launch(void* const* d_in, const int* in_sizes, int n_in,
                              void* d_out, int out_size)
{
    const float* x_q   = (const float*)d_in[0];
    const float* x_k   = (const float*)d_in[1];
    const float* Wq    = (const float*)d_in[2];
    const float* Wk    = (const float*)d_in[3];
    const float* Wv    = (const float*)d_in[4];
    const float* Wg    = (const float*)d_in[5];
    const float* bg    = (const float*)d_in[6];
    const float* Wo    = (const float*)d_in[7];
    const float* bo    = (const float*)d_in[8];
    const float* gamma = (const float*)d_in[9];
    const float* beta  = (const float*)d_in[10];
    float* out = (float*)d_out;

    // 1. LayerNorm both inputs
    ln_kernel<<<2*CM, 256>>>(x_q, x_k, gamma, beta);

    // 2. Projections
    dim3 gg(CD/64, CM/64);                 // (8, 128)
    gemm_nt_kernel<<<gg, 256>>>(0, Wq, nullptr, 0, nullptr);   // q
    gemm_nt_kernel<<<gg, 256>>>(1, Wk, nullptr, 0, nullptr);   // k
    gemm_nt_kernel<<<gg, 256>>>(2, Wv, nullptr, 0, nullptr);   // v
    gemm_nt_kernel<<<gg, 256>>>(3, Wg, bg,      1, nullptr);   // gate (sigmoid)

    // 3. Scores
    dim3 gs(CS/64, CS/64, CBH);            // (32, 32, 32)
    scores_kernel<<<gs, 256>>>();

    // 4. Softmax statistics (row and column), sums stored as reciprocals
    row_stats_kernel<<<CBH*CS/8, 256>>>();
    dim3 gc(CS/256, CBH);                  // (8, 32)
    col_stats_kernel<<<gc, 256>>>();

    // 5. PV with on-the-fly softmax product + fused gate
    dim3 gp(CS/64, CBH);                   // (32, 32)
    pv_kernel<<<gp, 256>>>();

    // 6. Output projection + bias -> d_out
    gemm_nt_kernel<<<gg, 256>>>(4, Wo, bo, 0, out);
}